// round 15
// baseline (speedup 1.0000x reference)
#include <cuda_runtime.h>
#include <cstdint>

#define BATCH  4
#define SEQ    2048
#define DMODEL 512
#define NHEAD  8
#define DEPTH  64
#define ROWS   (BATCH * SEQ)          // 8192
#define BH     (BATCH * NHEAD)        // 32
#define SCALE  0.125f                 // 1/sqrt(DEPTH), exact power of 2

// Scratch (device globals)
__device__ float g_xr[ROWS * DMODEL];       // tf32-rounded x
__device__ float g_wr[4 * DMODEL * DMODEL]; // tf32-rounded Wq,Wk,Wv,Wo
__device__ float g_q[BH * SEQ * DEPTH];     // tf32-rounded
__device__ float g_k[BH * SEQ * DEPTH];     // tf32-rounded
__device__ float g_v[BH * SEQ * DEPTH];     // tf32-rounded
__device__ float g_ctx[ROWS * DMODEL];      // tf32-rounded
__device__ float g_rowsum[BH * SEQ];

__device__ __forceinline__ uint32_t f2tf32(float x) {
    uint32_t r;
    asm("cvt.rna.tf32.f32 %0, %1;" : "=r"(r) : "f"(x));
    return r;
}
__device__ __forceinline__ float tf32r(float x) { return __uint_as_float(f2tf32(x)); }
__device__ __forceinline__ void mma8(float* c,
                                     uint32_t a0, uint32_t a1, uint32_t a2, uint32_t a3,
                                     uint32_t b0, uint32_t b1) {
    asm("mma.sync.aligned.m16n8k8.row.col.f32.tf32.tf32.f32 "
        "{%0,%1,%2,%3},{%4,%5,%6,%7},{%8,%9},{%0,%1,%2,%3};"
        : "+f"(c[0]), "+f"(c[1]), "+f"(c[2]), "+f"(c[3])
        : "r"(a0), "r"(a1), "r"(a2), "r"(a3), "r"(b0), "r"(b1));
}
__device__ __forceinline__ void cp_async16(uint32_t dst, const void* src) {
    asm volatile("cp.async.cg.shared.global [%0], [%1], 16;" :: "r"(dst), "l"(src));
}
__device__ __forceinline__ void ldsm_x4(uint32_t& r0, uint32_t& r1, uint32_t& r2, uint32_t& r3,
                                        uint32_t addr) {
    asm volatile("ldmatrix.sync.aligned.m8n8.x4.shared.b16 {%0,%1,%2,%3}, [%4];"
                 : "=r"(r0), "=r"(r1), "=r"(r2), "=r"(r3) : "r"(addr));
}

// ---------------------------------------------------------------------------
// K0: pre-round x and W matrices to tf32
// ---------------------------------------------------------------------------
__global__ __launch_bounds__(256) void round_prep(
    const float* __restrict__ x,
    const float* __restrict__ Wq, const float* __restrict__ Wk,
    const float* __restrict__ Wv, const float* __restrict__ Wo)
{
    const int idx = blockIdx.x * 256 + threadIdx.x;
    const int y = blockIdx.y;
    const float* src; float* dst; int n4;
    if (y == 0)      { src = x;  dst = g_xr;                n4 = ROWS * DMODEL / 4; }
    else if (y == 1) { src = Wq; dst = g_wr;                n4 = DMODEL * DMODEL / 4; }
    else if (y == 2) { src = Wk; dst = g_wr + DMODEL*DMODEL;     n4 = DMODEL * DMODEL / 4; }
    else if (y == 3) { src = Wv; dst = g_wr + 2*DMODEL*DMODEL;   n4 = DMODEL * DMODEL / 4; }
    else             { src = Wo; dst = g_wr + 3*DMODEL*DMODEL;   n4 = DMODEL * DMODEL / 4; }
    if (idx < n4) {
        float4 v = ((const float4*)src)[idx];
        v.x = tf32r(v.x); v.y = tf32r(v.y); v.z = tf32r(v.z); v.w = tf32r(v.w);
        ((float4*)dst)[idx] = v;
    }
}

// ---------------------------------------------------------------------------
// K1: tf32 GEMM, 128x128 CTA tile, BK=32, cp.async 3-stage, swizzled SMEM.
// (R11 proven version)
// ---------------------------------------------------------------------------
template<int MODE>
__global__ __launch_bounds__(256, 2) void gemm_tf32(
    const float* __restrict__ bias_q, const float* __restrict__ bias_k,
    const float* __restrict__ bias_v, float* __restrict__ outp)
{
    extern __shared__ float smf[];
    const uint32_t smem_u32 = (uint32_t)__cvta_generic_to_shared(smf);

    const float* Asrc; const float* W; const float* bias; float* out;
    if (MODE == 0) {
        Asrc = g_xr;
        const int z = blockIdx.z;
        W = g_wr + (size_t)z * DMODEL * DMODEL;
        if (z == 0)      { bias = bias_q; out = g_q; }
        else if (z == 1) { bias = bias_k; out = g_k; }
        else             { bias = bias_v; out = g_v; }
    } else {
        Asrc = g_ctx;
        W = g_wr + (size_t)3 * DMODEL * DMODEL;
        bias = bias_q; out = outp;
    }

    const int row0 = blockIdx.y * 128;
    const int col0 = blockIdx.x * 128;
    const int tid  = threadIdx.x;
    const int lane = tid & 31, wid = tid >> 5;
    const int wm = wid >> 1, wn = wid & 1;
    const int rquad = lane >> 2, cquad = lane & 3;

    const int a_r = tid >> 3, a_cw = tid & 7;
    const int b_r = tid >> 5, b_cw = tid & 31;

    #define STAGE(kt, s)                                                            \
    {                                                                               \
        const int k0_ = (kt) * 32;                                                  \
        const uint32_t ab = smem_u32 + (s) * 32768u;                                \
        const uint32_t bb = ab + 16384u;                                            \
        _Pragma("unroll")                                                           \
        for (int p = 0; p < 4; p++) {                                               \
            const int r = a_r + p * 32;                                             \
            cp_async16(ab + (uint32_t)((r * 8 + (a_cw ^ (r & 7))) * 16),            \
                       Asrc + (size_t)(row0 + r) * DMODEL + k0_ + a_cw * 4);        \
        }                                                                           \
        _Pragma("unroll")                                                           \
        for (int p = 0; p < 4; p++) {                                               \
            const int r = b_r + p * 8;                                              \
            cp_async16(bb + (uint32_t)((r * 32 + (b_cw ^ ((r & 3) << 1))) * 16),    \
                       W + (size_t)(k0_ + r) * DMODEL + col0 + b_cw * 4);           \
        }                                                                           \
        asm volatile("cp.async.commit_group;");                                     \
    }

    float c[2][8][4] = {};

    STAGE(0, 0);
    STAGE(1, 1);

    for (int it = 0; it < 16; it++) {
        if (it < 15) asm volatile("cp.async.wait_group 1;");
        else         asm volatile("cp.async.wait_group 0;");
        __syncthreads();

        const float* As = smf + (it % 3) * 8192;
        const float* Bs = As + 4096;

        #pragma unroll
        for (int ks = 0; ks < 4; ks++) {
            uint32_t a[2][4];
            const int sw0 = ((2 * ks) ^ rquad) * 4 + cquad;
            const int sw1 = ((2 * ks + 1) ^ rquad) * 4 + cquad;
            #pragma unroll
            for (int mi = 0; mi < 2; mi++) {
                const int m = wm * 32 + mi * 16 + rquad;
                a[mi][0] = __float_as_uint(As[m * 32 + sw0]);
                a[mi][1] = __float_as_uint(As[(m + 8) * 32 + sw0]);
                a[mi][2] = __float_as_uint(As[m * 32 + sw1]);
                a[mi][3] = __float_as_uint(As[(m + 8) * 32 + sw1]);
            }
            const int krow = ks * 8 + cquad;
            const int kx = cquad << 1;
            #pragma unroll
            for (int ni = 0; ni < 8; ni++) {
                const int nq = wn * 16 + ni * 2 + (rquad >> 2);
                const int sw = ((nq ^ kx) << 2) + (rquad & 3);
                const uint32_t b0 = __float_as_uint(Bs[krow * 128 + sw]);
                const uint32_t b1 = __float_as_uint(Bs[(krow + 4) * 128 + sw]);
                #pragma unroll
                for (int mi = 0; mi < 2; mi++)
                    mma8(c[mi][ni], a[mi][0], a[mi][1], a[mi][2], a[mi][3], b0, b1);
            }
        }

        if (it + 2 < 16) STAGE(it + 2, (it + 2) % 3);
    }

    #pragma unroll
    for (int mi = 0; mi < 2; mi++) {
        const int r = row0 + wm * 32 + mi * 16 + rquad;
        #pragma unroll
        for (int ni = 0; ni < 8; ni++) {
            const int col = col0 + wn * 64 + ni * 8 + cquad * 2;
            float v0 = c[mi][ni][0] + bias[col];
            float v1 = c[mi][ni][1] + bias[col + 1];
            float v2 = c[mi][ni][2] + bias[col];
            float v3 = c[mi][ni][3] + bias[col + 1];
            if (MODE == 0) {
                v0 = tf32r(v0); v1 = tf32r(v1); v2 = tf32r(v2); v3 = tf32r(v3);
                const int h = col >> 6;
                const int d = col & 63;
                const int b0i = r / SEQ, s0 = r % SEQ;
                *(float2*)(out + (size_t)((b0i * NHEAD + h) * SEQ + s0) * DEPTH + d) =
                    make_float2(v0, v1);
                const int b1i = (r + 8) / SEQ, s1 = (r + 8) % SEQ;
                *(float2*)(out + (size_t)((b1i * NHEAD + h) * SEQ + s1) * DEPTH + d) =
                    make_float2(v2, v3);
            } else {
                *(float2*)(out + (size_t)r * DMODEL + col)       = make_float2(v0, v1);
                *(float2*)(out + (size_t)(r + 8) * DMODEL + col) = make_float2(v2, v3);
            }
        }
    }
    #undef STAGE
}

// ---------------------------------------------------------------------------
// K2 (two phases): logits mma + exp.
// PHASE 0: rowsums only (no gmem stores).
// PHASE 1: writes NORMALIZED attn (e * inv) directly; no rowsum work.
// 128 q-rows/CTA, 32 k-tiles of 64 cols, double-buffered K, ldsm K-frags.
// ---------------------------------------------------------------------------
template<int PHASE>
__global__ __launch_bounds__(256) void logits_kernel(float* __restrict__ attn)
{
    __shared__ float S[128 * 68];
    __shared__ float rs[256];
    __shared__ float invsArr[128];
    const uint32_t S_u = (uint32_t)__cvta_generic_to_shared(S);

    const int qrow0 = blockIdx.x * 128;
    const int bh    = blockIdx.y;
    const float* qg = g_q + (size_t)bh * SEQ * DEPTH;
    const float* kg = g_k + (size_t)bh * SEQ * DEPTH;
    float* outp     = attn + (size_t)bh * SEQ * SEQ;

    const int tid  = threadIdx.x;
    const int lane = tid & 31, wid = tid >> 5;
    const int wm = wid >> 1, wn = wid & 1;
    const int rquad = lane >> 2, cquad = lane & 3;
    const int prow = tid >> 4, pc4 = tid & 15;

    const int bl_row = (lane & 7) + ((lane >> 4) & 1) * 8;
    const int bl_cg  = (lane >> 3) & 1;
    uint32_t kAddr[2];
    #pragma unroll
    for (int np = 0; np < 2; np++)
        kAddr[np] = S_u + (uint32_t)(((wn * 32 + np * 16 + bl_row) * 68 + bl_cg * 4) * 4);

    #pragma unroll
    for (int p = 0; p < 8; p++) {
        int row = prow + p * 16;
        *(float4*)(S + row * 68 + pc4 * 4) =
            *(const float4*)(qg + (size_t)(qrow0 + row) * DEPTH + pc4 * 4);
    }
    if (PHASE == 1 && tid < 128)
        invsArr[tid] = 1.0f / g_rowsum[(size_t)bh * SEQ + qrow0 + tid];
    __syncthreads();

    uint32_t qa[2][8][4];
    #pragma unroll
    for (int mi = 0; mi < 2; mi++)
        #pragma unroll
        for (int ks = 0; ks < 8; ks++) {
            const float* qp = S + (wm * 32 + mi * 16 + rquad) * 68 + ks * 8 + cquad;
            qa[mi][ks][0] = __float_as_uint(qp[0] * SCALE);
            qa[mi][ks][1] = __float_as_uint(qp[8 * 68] * SCALE);
            qa[mi][ks][2] = __float_as_uint(qp[4] * SCALE);
            qa[mi][ks][3] = __float_as_uint(qp[8 * 68 + 4] * SCALE);
        }

    float4 pk[4];
    #pragma unroll
    for (int p = 0; p < 4; p++)
        pk[p] = *(const float4*)(kg + (size_t)(prow + p * 16) * DEPTH + pc4 * 4);
    __syncthreads();
    #pragma unroll
    for (int p = 0; p < 4; p++)
        *(float4*)(S + (prow + p * 16) * 68 + pc4 * 4) = pk[p];

    float rowpart[4] = {0.f, 0.f, 0.f, 0.f};

    for (int it = 0; it < 32; it++) {
        __syncthreads();
        if (it + 1 < 32) {
            const int kcol0 = (it + 1) * 64;
            #pragma unroll
            for (int p = 0; p < 4; p++)
                pk[p] = *(const float4*)(kg + (size_t)(kcol0 + prow + p * 16) * DEPTH + pc4 * 4);
        }
        const uint32_t pofs = (uint32_t)((it & 1) * (64 * 68 * 4));
        const int kcol0 = it * 64;

        float c[2][4][4] = {};
        #pragma unroll
        for (int ks = 0; ks < 8; ks++) {
            uint32_t b[4][2];
            ldsm_x4(b[0][0], b[0][1], b[1][0], b[1][1], kAddr[0] + pofs + ks * 32);
            ldsm_x4(b[2][0], b[2][1], b[3][0], b[3][1], kAddr[1] + pofs + ks * 32);
            #pragma unroll
            for (int mi = 0; mi < 2; mi++)
                #pragma unroll
                for (int ni = 0; ni < 4; ni++)
                    mma8(c[mi][ni], qa[mi][ks][0], qa[mi][ks][1], qa[mi][ks][2], qa[mi][ks][3],
                         b[ni][0], b[ni][1]);
        }

        #pragma unroll
        for (int mi = 0; mi < 2; mi++) {
            const int lrow = wm * 32 + mi * 16 + rquad;
            const int rA = qrow0 + lrow;
            #pragma unroll
            for (int ni = 0; ni < 4; ni++) {
                const int col = kcol0 + wn * 32 + ni * 8 + cquad * 2;
                float e0 = __expf(c[mi][ni][0]);
                float e1 = __expf(c[mi][ni][1]);
                float e2 = __expf(c[mi][ni][2]);
                float e3 = __expf(c[mi][ni][3]);
                if (PHASE == 0) {
                    rowpart[mi * 2 + 0] += e0 + e1;
                    rowpart[mi * 2 + 1] += e2 + e3;
                } else {
                    const float iA = invsArr[lrow];
                    const float iB = invsArr[lrow + 8];
                    *(float2*)(outp + (size_t)rA * SEQ + col) =
                        make_float2(e0 * iA, e1 * iA);
                    *(float2*)(outp + (size_t)(rA + 8) * SEQ + col) =
                        make_float2(e2 * iB, e3 * iB);
                }
            }
        }

        if (it + 1 < 32) {
            float* Kn = S + ((it + 1) & 1) * (64 * 68);
            #pragma unroll
            for (int p = 0; p < 4; p++)
                *(float4*)(Kn + (prow + p * 16) * 68 + pc4 * 4) = pk[p];
        }
    }

    if (PHASE == 0) {
        #pragma unroll
        for (int i = 0; i < 4; i++) {
            float v = rowpart[i];
            v += __shfl_xor_sync(0xffffffffu, v, 1);
            v += __shfl_xor_sync(0xffffffffu, v, 2);
            if (cquad == 0) {
                int rloc = wm * 32 + (i >> 1) * 16 + (i & 1) * 8 + rquad;
                rs[wn * 128 + rloc] = v;
            }
        }
        __syncthreads();
        if (tid < 128)
            g_rowsum[(size_t)bh * SEQ + qrow0 + tid] = rs[tid] + rs[128 + tid];
    }
}

// ---------------------------------------------------------------------------
// K3': ctx = (normalized attn) @ v. Read-only attn; no normalize/STG in loop.
// 64 q-rows/CTA; 8 warps = 2m x 4n, warp tile 32x16. A-frags via ldmatrix.x4.
// ---------------------------------------------------------------------------
__global__ __launch_bounds__(256) void ctx_kernel(const float* __restrict__ attn)
{
    extern __shared__ float sm[];
    float* Ab = sm;                    // [2][64*68] attn (tf32-rounded)
    float* Vb = sm + 2 * 64 * 68;      // [2][64*68]
    const uint32_t sm_u = (uint32_t)__cvta_generic_to_shared(sm);

    const int qrow0 = blockIdx.x * 64;
    const int bh    = blockIdx.y;
    const int b = bh >> 3, h = bh & 7;
    const float* ap = attn + (size_t)bh * SEQ * SEQ;
    const float* vg = g_v + (size_t)bh * SEQ * DEPTH;

    const int tid = threadIdx.x, lane = tid & 31, wid = tid >> 5;
    const int wm = wid >> 2, wn = wid & 3;
    const int rquad = lane >> 2, cquad = lane & 3;
    const int prow = tid >> 4, pc4 = tid & 15;

    const int al_row = (lane & 7) + ((lane >> 3) & 1) * 8;
    const int al_cg  = (lane >> 4) & 1;
    uint32_t aAddr[2];
    #pragma unroll
    for (int mi = 0; mi < 2; mi++)
        aAddr[mi] = sm_u + (uint32_t)(((wm * 32 + mi * 16 + al_row) * 68 + al_cg * 4) * 4);

    float4 pa[4], pv[4];
    #pragma unroll
    for (int p = 0; p < 4; p++) {
        int row = prow + p * 16;
        pa[p] = *(const float4*)(ap + (size_t)(qrow0 + row) * SEQ + pc4 * 4);
        pv[p] = *(const float4*)(vg + (size_t)row * DEPTH + pc4 * 4);
    }
    #pragma unroll
    for (int p = 0; p < 4; p++) {
        int row = prow + p * 16;
        float4 rv;
        rv.x = tf32r(pa[p].x); rv.y = tf32r(pa[p].y);
        rv.z = tf32r(pa[p].z); rv.w = tf32r(pa[p].w);
        *(float4*)(Ab + row * 68 + pc4 * 4) = rv;
        *(float4*)(Vb + row * 68 + pc4 * 4) = pv[p];
    }

    float c[2][2][4] = {};

    for (int it = 0; it < 32; it++) {
        __syncthreads();
        if (it + 1 < 32) {
            const int s0 = (it + 1) * 64;
            #pragma unroll
            for (int p = 0; p < 4; p++) {
                int row = prow + p * 16;
                pa[p] = *(const float4*)(ap + (size_t)(qrow0 + row) * SEQ + s0 + pc4 * 4);
                pv[p] = *(const float4*)(vg + (size_t)(s0 + row) * DEPTH + pc4 * 4);
            }
        }
        const uint32_t pofs = (uint32_t)((it & 1) * (64 * 68 * 4));
        const float* Vs = Vb + (it & 1) * (64 * 68);

        #pragma unroll
        for (int ks = 0; ks < 8; ks++) {
            uint32_t a[2][4];
            ldsm_x4(a[0][0], a[0][1], a[0][2], a[0][3], aAddr[0] + pofs + ks * 32);
            ldsm_x4(a[1][0], a[1][1], a[1][2], a[1][3], aAddr[1] + pofs + ks * 32);
            uint32_t bb[2][2];
            #pragma unroll
            for (int ni = 0; ni < 2; ni++) {
                const float* vp = Vs + (ks * 8 + cquad) * 68 + wn * 16 + ni * 8 + rquad;
                bb[ni][0] = __float_as_uint(vp[0]);
                bb[ni][1] = __float_as_uint(vp[4 * 68]);
            }
            #pragma unroll
            for (int mi = 0; mi < 2; mi++)
                #pragma unroll
                for (int ni = 0; ni < 2; ni++)
                    mma8(c[mi][ni], a[mi][0], a[mi][1], a[mi][2], a[mi][3],
                         bb[ni][0], bb[ni][1]);
        }

        if (it + 1 < 32) {
            float* An = Ab + ((it + 1) & 1) * (64 * 68);
            float* Vn = Vb + ((it + 1) & 1) * (64 * 68);
            #pragma unroll
            for (int p = 0; p < 4; p++) {
                int row = prow + p * 16;
                float4 rv;
                rv.x = tf32r(pa[p].x); rv.y = tf32r(pa[p].y);
                rv.z = tf32r(pa[p].z); rv.w = tf32r(pa[p].w);
                *(float4*)(An + row * 68 + pc4 * 4) = rv;
                *(float4*)(Vn + row * 68 + pc4 * 4) = pv[p];
            }
        }
    }

    // epilogue: round ctx to tf32 (input of out-proj), write
    #pragma unroll
    for (int mi = 0; mi < 2; mi++) {
        const int r = qrow0 + wm * 32 + mi * 16 + rquad;
        #pragma unroll
        for (int ni = 0; ni < 2; ni++) {
            const int col = h * 64 + wn * 16 + ni * 8 + cquad * 2;
            float u0 = tf32r(c[mi][ni][0]);
            float u1 = tf32r(c[mi][ni][1]);
            float u2 = tf32r(c[mi][ni][2]);
            float u3 = tf32r(c[mi][ni][3]);
            *(float2*)(g_ctx + (size_t)(b * SEQ + r) * DMODEL + col)       = make_float2(u0, u1);
            *(float2*)(g_ctx + (size_t)(b * SEQ + r + 8) * DMODEL + col) = make_float2(u2, u3);
        }
    }
}

// ---------------------------------------------------------------------------
extern "C" void kernel_launch(void* const* d_in, const int* in_sizes, int n_in,
                              void* d_out, int out_size)
{
    const float* x  = (const float*)d_in[0];
    const float* Wq = (const float*)d_in[1];
    const float* bq = (const float*)d_in[2];
    const float* Wk = (const float*)d_in[3];
    const float* bk = (const float*)d_in[4];
    const float* Wv = (const float*)d_in[5];
    const float* bv = (const float*)d_in[6];
    const float* Wo = (const float*)d_in[7];
    const float* bo = (const float*)d_in[8];

    float* out  = (float*)d_out;
    float* attn = out + (size_t)ROWS * DMODEL;

    const int smem_gemm = 3 * 8192 * 4;                  // 98304
    const int smem_k3   = (2 * 64 * 68 + 2 * 64 * 68) * 4;  // 69632
    cudaFuncSetAttribute(gemm_tf32<0>, cudaFuncAttributeMaxDynamicSharedMemorySize, smem_gemm);
    cudaFuncSetAttribute(gemm_tf32<1>, cudaFuncAttributeMaxDynamicSharedMemorySize, smem_gemm);
    cudaFuncSetAttribute(ctx_kernel, cudaFuncAttributeMaxDynamicSharedMemorySize, smem_k3);

    round_prep<<<dim3(ROWS * DMODEL / 4 / 256, 5), 256>>>(x, Wq, Wk, Wv, Wo);
    gemm_tf32<0><<<dim3(DMODEL / 128, ROWS / 128, 3), 256, smem_gemm>>>(bq, bk, bv, nullptr);
    logits_kernel<0><<<dim3(SEQ / 128, BH), 256>>>(attn);
    logits_kernel<1><<<dim3(SEQ / 128, BH), 256>>>(attn);
    ctx_kernel<<<dim3(SEQ / 64, BH), 256, smem_k3>>>(attn);
    gemm_tf32<1><<<dim3(DMODEL / 128, ROWS / 128, 1), 256, smem_gemm>>>(bo, nullptr, nullptr, out);
}

// round 16
// speedup vs baseline: 1.0936x; 1.0936x over previous
#include <cuda_runtime.h>
#include <cstdint>

#define BATCH  4
#define SEQ    2048
#define DMODEL 512
#define NHEAD  8
#define DEPTH  64
#define ROWS   (BATCH * SEQ)          // 8192
#define BH     (BATCH * NHEAD)        // 32
#define SCALE  0.125f                 // 1/sqrt(DEPTH), exact power of 2

// Scratch (device globals)
__device__ float g_xr[ROWS * DMODEL];       // tf32-rounded x
__device__ float g_wr[4 * DMODEL * DMODEL]; // tf32-rounded Wq,Wk,Wv,Wo
__device__ float g_q[BH * SEQ * DEPTH];     // tf32-rounded
__device__ float g_k[BH * SEQ * DEPTH];     // tf32-rounded
__device__ float g_v[BH * SEQ * DEPTH];     // tf32-rounded
__device__ float g_ctx[ROWS * DMODEL];      // tf32-rounded (by K3 epilogue)
__device__ float g_rowsum[BH * SEQ];

__device__ __forceinline__ uint32_t f2tf32(float x) {
    uint32_t r;
    asm("cvt.rna.tf32.f32 %0, %1;" : "=r"(r) : "f"(x));
    return r;
}
__device__ __forceinline__ float tf32r(float x) { return __uint_as_float(f2tf32(x)); }
__device__ __forceinline__ void mma8(float* c,
                                     uint32_t a0, uint32_t a1, uint32_t a2, uint32_t a3,
                                     uint32_t b0, uint32_t b1) {
    asm("mma.sync.aligned.m16n8k8.row.col.f32.tf32.tf32.f32 "
        "{%0,%1,%2,%3},{%4,%5,%6,%7},{%8,%9},{%0,%1,%2,%3};"
        : "+f"(c[0]), "+f"(c[1]), "+f"(c[2]), "+f"(c[3])
        : "r"(a0), "r"(a1), "r"(a2), "r"(a3), "r"(b0), "r"(b1));
}
__device__ __forceinline__ void cp_async16(uint32_t dst, const void* src) {
    asm volatile("cp.async.cg.shared.global [%0], [%1], 16;" :: "r"(dst), "l"(src));
}
__device__ __forceinline__ void ldsm_x4(uint32_t& r0, uint32_t& r1, uint32_t& r2, uint32_t& r3,
                                        uint32_t addr) {
    asm volatile("ldmatrix.sync.aligned.m8n8.x4.shared.b16 {%0,%1,%2,%3}, [%4];"
                 : "=r"(r0), "=r"(r1), "=r"(r2), "=r"(r3) : "r"(addr));
}

// ---------------------------------------------------------------------------
// K0: pre-round x and W matrices to tf32 (one-time, elementwise)
// ---------------------------------------------------------------------------
__global__ __launch_bounds__(256) void round_prep(
    const float* __restrict__ x,
    const float* __restrict__ Wq, const float* __restrict__ Wk,
    const float* __restrict__ Wv, const float* __restrict__ Wo)
{
    const int idx = blockIdx.x * 256 + threadIdx.x;
    const int y = blockIdx.y;
    const float* src; float* dst; int n4;
    if (y == 0)      { src = x;  dst = g_xr;                n4 = ROWS * DMODEL / 4; }
    else if (y == 1) { src = Wq; dst = g_wr;                n4 = DMODEL * DMODEL / 4; }
    else if (y == 2) { src = Wk; dst = g_wr + DMODEL*DMODEL;     n4 = DMODEL * DMODEL / 4; }
    else if (y == 3) { src = Wv; dst = g_wr + 2*DMODEL*DMODEL;   n4 = DMODEL * DMODEL / 4; }
    else             { src = Wo; dst = g_wr + 3*DMODEL*DMODEL;   n4 = DMODEL * DMODEL / 4; }
    if (idx < n4) {
        float4 v = ((const float4*)src)[idx];
        v.x = tf32r(v.x); v.y = tf32r(v.y); v.z = tf32r(v.z); v.w = tf32r(v.w);
        ((float4*)dst)[idx] = v;
    }
}

// ---------------------------------------------------------------------------
// K1: tf32 GEMM, 128x128 CTA tile, BK=32, cp.async 3-stage, swizzled SMEM.
// (R11 proven version)
// ---------------------------------------------------------------------------
template<int MODE>
__global__ __launch_bounds__(256, 2) void gemm_tf32(
    const float* __restrict__ bias_q, const float* __restrict__ bias_k,
    const float* __restrict__ bias_v, float* __restrict__ outp)
{
    extern __shared__ float smf[];
    const uint32_t smem_u32 = (uint32_t)__cvta_generic_to_shared(smf);

    const float* Asrc; const float* W; const float* bias; float* out;
    if (MODE == 0) {
        Asrc = g_xr;
        const int z = blockIdx.z;
        W = g_wr + (size_t)z * DMODEL * DMODEL;
        if (z == 0)      { bias = bias_q; out = g_q; }
        else if (z == 1) { bias = bias_k; out = g_k; }
        else             { bias = bias_v; out = g_v; }
    } else {
        Asrc = g_ctx;
        W = g_wr + (size_t)3 * DMODEL * DMODEL;
        bias = bias_q; out = outp;
    }

    const int row0 = blockIdx.y * 128;
    const int col0 = blockIdx.x * 128;
    const int tid  = threadIdx.x;
    const int lane = tid & 31, wid = tid >> 5;
    const int wm = wid >> 1, wn = wid & 1;
    const int rquad = lane >> 2, cquad = lane & 3;

    const int a_r = tid >> 3, a_cw = tid & 7;
    const int b_r = tid >> 5, b_cw = tid & 31;

    #define STAGE(kt, s)                                                            \
    {                                                                               \
        const int k0_ = (kt) * 32;                                                  \
        const uint32_t ab = smem_u32 + (s) * 32768u;                                \
        const uint32_t bb = ab + 16384u;                                            \
        _Pragma("unroll")                                                           \
        for (int p = 0; p < 4; p++) {                                               \
            const int r = a_r + p * 32;                                             \
            cp_async16(ab + (uint32_t)((r * 8 + (a_cw ^ (r & 7))) * 16),            \
                       Asrc + (size_t)(row0 + r) * DMODEL + k0_ + a_cw * 4);        \
        }                                                                           \
        _Pragma("unroll")                                                           \
        for (int p = 0; p < 4; p++) {                                               \
            const int r = b_r + p * 8;                                              \
            cp_async16(bb + (uint32_t)((r * 32 + (b_cw ^ ((r & 3) << 1))) * 16),    \
                       W + (size_t)(k0_ + r) * DMODEL + col0 + b_cw * 4);           \
        }                                                                           \
        asm volatile("cp.async.commit_group;");                                     \
    }

    float c[2][8][4] = {};

    STAGE(0, 0);
    STAGE(1, 1);

    for (int it = 0; it < 16; it++) {
        if (it < 15) asm volatile("cp.async.wait_group 1;");
        else         asm volatile("cp.async.wait_group 0;");
        __syncthreads();

        const float* As = smf + (it % 3) * 8192;
        const float* Bs = As + 4096;

        #pragma unroll
        for (int ks = 0; ks < 4; ks++) {
            uint32_t a[2][4];
            const int sw0 = ((2 * ks) ^ rquad) * 4 + cquad;
            const int sw1 = ((2 * ks + 1) ^ rquad) * 4 + cquad;
            #pragma unroll
            for (int mi = 0; mi < 2; mi++) {
                const int m = wm * 32 + mi * 16 + rquad;
                a[mi][0] = __float_as_uint(As[m * 32 + sw0]);
                a[mi][1] = __float_as_uint(As[(m + 8) * 32 + sw0]);
                a[mi][2] = __float_as_uint(As[m * 32 + sw1]);
                a[mi][3] = __float_as_uint(As[(m + 8) * 32 + sw1]);
            }
            const int krow = ks * 8 + cquad;
            const int kx = cquad << 1;
            #pragma unroll
            for (int ni = 0; ni < 8; ni++) {
                const int nq = wn * 16 + ni * 2 + (rquad >> 2);
                const int sw = ((nq ^ kx) << 2) + (rquad & 3);
                const uint32_t b0 = __float_as_uint(Bs[krow * 128 + sw]);
                const uint32_t b1 = __float_as_uint(Bs[(krow + 4) * 128 + sw]);
                #pragma unroll
                for (int mi = 0; mi < 2; mi++)
                    mma8(c[mi][ni], a[mi][0], a[mi][1], a[mi][2], a[mi][3], b0, b1);
            }
        }

        if (it + 2 < 16) STAGE(it + 2, (it + 2) % 3);
    }

    #pragma unroll
    for (int mi = 0; mi < 2; mi++) {
        const int r = row0 + wm * 32 + mi * 16 + rquad;
        #pragma unroll
        for (int ni = 0; ni < 8; ni++) {
            const int col = col0 + wn * 64 + ni * 8 + cquad * 2;
            float v0 = c[mi][ni][0] + bias[col];
            float v1 = c[mi][ni][1] + bias[col + 1];
            float v2 = c[mi][ni][2] + bias[col];
            float v3 = c[mi][ni][3] + bias[col + 1];
            if (MODE == 0) {
                v0 = tf32r(v0); v1 = tf32r(v1); v2 = tf32r(v2); v3 = tf32r(v3);
                const int h = col >> 6;
                const int d = col & 63;
                const int b0i = r / SEQ, s0 = r % SEQ;
                *(float2*)(out + (size_t)((b0i * NHEAD + h) * SEQ + s0) * DEPTH + d) =
                    make_float2(v0, v1);
                const int b1i = (r + 8) / SEQ, s1 = (r + 8) % SEQ;
                *(float2*)(out + (size_t)((b1i * NHEAD + h) * SEQ + s1) * DEPTH + d) =
                    make_float2(v2, v3);
            } else {
                *(float2*)(out + (size_t)r * DMODEL + col)       = make_float2(v0, v1);
                *(float2*)(out + (size_t)(r + 8) * DMODEL + col) = make_float2(v2, v3);
            }
        }
    }
    #undef STAGE
}

// ---------------------------------------------------------------------------
// K2: attn_raw = exp((q*SCALE)@k^T), rowsums. Q in registers (SCALE folded).
// 128 q-rows/CTA, 32 k-tiles of 64 cols, double-buffered K in reused SMEM.
// K-fragments via ldmatrix.x4. (R11 version)
// ---------------------------------------------------------------------------
__global__ __launch_bounds__(256) void logits_exp_kernel(float* __restrict__ attn)
{
    __shared__ float S[128 * 68];
    __shared__ float rs[256];
    const uint32_t S_u = (uint32_t)__cvta_generic_to_shared(S);

    const int qrow0 = blockIdx.x * 128;
    const int bh    = blockIdx.y;
    const float* qg = g_q + (size_t)bh * SEQ * DEPTH;
    const float* kg = g_k + (size_t)bh * SEQ * DEPTH;
    float* outp     = attn + (size_t)bh * SEQ * SEQ;

    const int tid  = threadIdx.x;
    const int lane = tid & 31, wid = tid >> 5;
    const int wm = wid >> 1, wn = wid & 1;
    const int rquad = lane >> 2, cquad = lane & 3;
    const int prow = tid >> 4, pc4 = tid & 15;

    const int bl_row = (lane & 7) + ((lane >> 4) & 1) * 8;
    const int bl_cg  = (lane >> 3) & 1;
    uint32_t kAddr[2];
    #pragma unroll
    for (int np = 0; np < 2; np++)
        kAddr[np] = S_u + (uint32_t)(((wn * 32 + np * 16 + bl_row) * 68 + bl_cg * 4) * 4);

    #pragma unroll
    for (int p = 0; p < 8; p++) {
        int row = prow + p * 16;
        *(float4*)(S + row * 68 + pc4 * 4) =
            *(const float4*)(qg + (size_t)(qrow0 + row) * DEPTH + pc4 * 4);
    }
    __syncthreads();

    uint32_t qa[2][8][4];
    #pragma unroll
    for (int mi = 0; mi < 2; mi++)
        #pragma unroll
        for (int ks = 0; ks < 8; ks++) {
            const float* qp = S + (wm * 32 + mi * 16 + rquad) * 68 + ks * 8 + cquad;
            qa[mi][ks][0] = __float_as_uint(qp[0] * SCALE);
            qa[mi][ks][1] = __float_as_uint(qp[8 * 68] * SCALE);
            qa[mi][ks][2] = __float_as_uint(qp[4] * SCALE);
            qa[mi][ks][3] = __float_as_uint(qp[8 * 68 + 4] * SCALE);
        }

    float4 pk[4];
    #pragma unroll
    for (int p = 0; p < 4; p++)
        pk[p] = *(const float4*)(kg + (size_t)(prow + p * 16) * DEPTH + pc4 * 4);
    __syncthreads();
    #pragma unroll
    for (int p = 0; p < 4; p++)
        *(float4*)(S + (prow + p * 16) * 68 + pc4 * 4) = pk[p];

    float rowpart[4] = {0.f, 0.f, 0.f, 0.f};

    for (int it = 0; it < 32; it++) {
        __syncthreads();
        if (it + 1 < 32) {
            const int kcol0 = (it + 1) * 64;
            #pragma unroll
            for (int p = 0; p < 4; p++)
                pk[p] = *(const float4*)(kg + (size_t)(kcol0 + prow + p * 16) * DEPTH + pc4 * 4);
        }
        const uint32_t pofs = (uint32_t)((it & 1) * (64 * 68 * 4));
        const int kcol0 = it * 64;

        float c[2][4][4] = {};
        #pragma unroll
        for (int ks = 0; ks < 8; ks++) {
            uint32_t b[4][2];
            ldsm_x4(b[0][0], b[0][1], b[1][0], b[1][1], kAddr[0] + pofs + ks * 32);
            ldsm_x4(b[2][0], b[2][1], b[3][0], b[3][1], kAddr[1] + pofs + ks * 32);
            #pragma unroll
            for (int mi = 0; mi < 2; mi++)
                #pragma unroll
                for (int ni = 0; ni < 4; ni++)
                    mma8(c[mi][ni], qa[mi][ks][0], qa[mi][ks][1], qa[mi][ks][2], qa[mi][ks][3],
                         b[ni][0], b[ni][1]);
        }

        #pragma unroll
        for (int mi = 0; mi < 2; mi++) {
            const int rA = qrow0 + wm * 32 + mi * 16 + rquad;
            #pragma unroll
            for (int ni = 0; ni < 4; ni++) {
                const int col = kcol0 + wn * 32 + ni * 8 + cquad * 2;
                float e0 = __expf(c[mi][ni][0]);
                float e1 = __expf(c[mi][ni][1]);
                float e2 = __expf(c[mi][ni][2]);
                float e3 = __expf(c[mi][ni][3]);
                rowpart[mi * 2 + 0] += e0 + e1;
                rowpart[mi * 2 + 1] += e2 + e3;
                *(float2*)(outp + (size_t)rA * SEQ + col)       = make_float2(e0, e1);
                *(float2*)(outp + (size_t)(rA + 8) * SEQ + col) = make_float2(e2, e3);
            }
        }

        if (it + 1 < 32) {
            float* Kn = S + ((it + 1) & 1) * (64 * 68);
            #pragma unroll
            for (int p = 0; p < 4; p++)
                *(float4*)(Kn + (prow + p * 16) * 68 + pc4 * 4) = pk[p];
        }
    }

    #pragma unroll
    for (int i = 0; i < 4; i++) {
        float v = rowpart[i];
        v += __shfl_xor_sync(0xffffffffu, v, 1);
        v += __shfl_xor_sync(0xffffffffu, v, 2);
        if (cquad == 0) {
            int rloc = wm * 32 + (i >> 1) * 16 + (i & 1) * 8 + rquad;
            rs[wn * 128 + rloc] = v;
        }
    }
    __syncthreads();
    if (tid < 128)
        g_rowsum[(size_t)bh * SEQ + qrow0 + tid] = rs[tid] + rs[128 + tid];
}

// ---------------------------------------------------------------------------
// K3: ctx = (raw attn @ v) * inv; normalized attn written from prefetch regs.
// 64 q-rows/CTA; 8 warps = 2m x 4n, warp tile 32x16. A-frags via ldmatrix.x4.
// (R11 version) + launch_bounds(256,3) + full SMEM carveout for 3 CTAs/SM.
// ---------------------------------------------------------------------------
__global__ __launch_bounds__(256, 3) void ctx_norm_kernel(float* __restrict__ attn)
{
    extern __shared__ float sm[];
    float* Ab   = sm;                    // [2][64*68]
    float* Vb   = sm + 2 * 64 * 68;      // [2][64*68]
    float* invs = Vb + 2 * 64 * 68;      // [64]
    const uint32_t sm_u = (uint32_t)__cvta_generic_to_shared(sm);

    const int qrow0 = blockIdx.x * 64;
    const int bh    = blockIdx.y;
    const int b = bh >> 3, h = bh & 7;
    float* ap       = attn + (size_t)bh * SEQ * SEQ;
    const float* vg = g_v + (size_t)bh * SEQ * DEPTH;

    const int tid = threadIdx.x, lane = tid & 31, wid = tid >> 5;
    const int wm = wid >> 2, wn = wid & 3;
    const int rquad = lane >> 2, cquad = lane & 3;
    const int prow = tid >> 4, pc4 = tid & 15;

    const int al_row = (lane & 7) + ((lane >> 3) & 1) * 8;
    const int al_cg  = (lane >> 4) & 1;
    uint32_t aAddr[2];
    #pragma unroll
    for (int mi = 0; mi < 2; mi++)
        aAddr[mi] = sm_u + (uint32_t)(((wm * 32 + mi * 16 + al_row) * 68 + al_cg * 4) * 4);

    if (tid < 64)
        invs[tid] = 1.0f / g_rowsum[(size_t)bh * SEQ + qrow0 + tid];
    __syncthreads();

    float4 pa[4], pv[4];
    #pragma unroll
    for (int p = 0; p < 4; p++) {
        int row = prow + p * 16;
        pa[p] = *(const float4*)(ap + (size_t)(qrow0 + row) * SEQ + pc4 * 4);
        pv[p] = *(const float4*)(vg + (size_t)row * DEPTH + pc4 * 4);
    }
    #pragma unroll
    for (int p = 0; p < 4; p++) {
        int row = prow + p * 16;
        float inv = invs[row];
        float4 w = pa[p];
        w.x *= inv; w.y *= inv; w.z *= inv; w.w *= inv;
        *(float4*)(ap + (size_t)(qrow0 + row) * SEQ + pc4 * 4) = w;
        float4 rv;
        rv.x = tf32r(pa[p].x); rv.y = tf32r(pa[p].y);
        rv.z = tf32r(pa[p].z); rv.w = tf32r(pa[p].w);
        *(float4*)(Ab + row * 68 + pc4 * 4) = rv;
        *(float4*)(Vb + row * 68 + pc4 * 4) = pv[p];
    }

    float c[2][2][4] = {};

    for (int it = 0; it < 32; it++) {
        __syncthreads();
        if (it + 1 < 32) {
            const int s0 = (it + 1) * 64;
            #pragma unroll
            for (int p = 0; p < 4; p++) {
                int row = prow + p * 16;
                pa[p] = *(const float4*)(ap + (size_t)(qrow0 + row) * SEQ + s0 + pc4 * 4);
                pv[p] = *(const float4*)(vg + (size_t)(s0 + row) * DEPTH + pc4 * 4);
            }
        }
        const uint32_t pofs = (uint32_t)((it & 1) * (64 * 68 * 4));
        const float* Vs = Vb + (it & 1) * (64 * 68);

        #pragma unroll
        for (int ks = 0; ks < 8; ks++) {
            uint32_t a[2][4];
            ldsm_x4(a[0][0], a[0][1], a[0][2], a[0][3], aAddr[0] + pofs + ks * 32);
            ldsm_x4(a[1][0], a[1][1], a[1][2], a[1][3], aAddr[1] + pofs + ks * 32);
            uint32_t bb[2][2];
            #pragma unroll
            for (int ni = 0; ni < 2; ni++) {
                const float* vp = Vs + (ks * 8 + cquad) * 68 + wn * 16 + ni * 8 + rquad;
                bb[ni][0] = __float_as_uint(vp[0]);
                bb[ni][1] = __float_as_uint(vp[4 * 68]);
            }
            #pragma unroll
            for (int mi = 0; mi < 2; mi++)
                #pragma unroll
                for (int ni = 0; ni < 2; ni++)
                    mma8(c[mi][ni], a[mi][0], a[mi][1], a[mi][2], a[mi][3],
                         bb[ni][0], bb[ni][1]);
        }

        if (it + 1 < 32) {
            const int s0 = (it + 1) * 64;
            float* An = Ab + ((it + 1) & 1) * (64 * 68);
            float* Vn = Vb + ((it + 1) & 1) * (64 * 68);
            #pragma unroll
            for (int p = 0; p < 4; p++) {
                int row = prow + p * 16;
                float inv = invs[row];
                float4 w = pa[p];
                w.x *= inv; w.y *= inv; w.z *= inv; w.w *= inv;
                *(float4*)(ap + (size_t)(qrow0 + row) * SEQ + s0 + pc4 * 4) = w;
                float4 rv;
                rv.x = tf32r(pa[p].x); rv.y = tf32r(pa[p].y);
                rv.z = tf32r(pa[p].z); rv.w = tf32r(pa[p].w);
                *(float4*)(An + row * 68 + pc4 * 4) = rv;
                *(float4*)(Vn + row * 68 + pc4 * 4) = pv[p];
            }
        }
    }

    // epilogue: scale ctx by inv, round to tf32 (input of out-proj), write
    #pragma unroll
    for (int mi = 0; mi < 2; mi++) {
        const int rloc = wm * 32 + mi * 16 + rquad;
        const float i0 = invs[rloc], i1 = invs[rloc + 8];
        const int r = qrow0 + rloc;
        #pragma unroll
        for (int ni = 0; ni < 2; ni++) {
            const int col = h * 64 + wn * 16 + ni * 8 + cquad * 2;
            float u0 = tf32r(c[mi][ni][0] * i0);
            float u1 = tf32r(c[mi][ni][1] * i0);
            float u2 = tf32r(c[mi][ni][2] * i1);
            float u3 = tf32r(c[mi][ni][3] * i1);
            *(float2*)(g_ctx + (size_t)(b * SEQ + r) * DMODEL + col)       = make_float2(u0, u1);
            *(float2*)(g_ctx + (size_t)(b * SEQ + r + 8) * DMODEL + col) = make_float2(u2, u3);
        }
    }
}

// ---------------------------------------------------------------------------
extern "C" void kernel_launch(void* const* d_in, const int* in_sizes, int n_in,
                              void* d_out, int out_size)
{
    const float* x  = (const float*)d_in[0];
    const float* Wq = (const float*)d_in[1];
    const float* bq = (const float*)d_in[2];
    const float* Wk = (const float*)d_in[3];
    const float* bk = (const float*)d_in[4];
    const float* Wv = (const float*)d_in[5];
    const float* bv = (const float*)d_in[6];
    const float* Wo = (const float*)d_in[7];
    const float* bo = (const float*)d_in[8];

    float* out  = (float*)d_out;
    float* attn = out + (size_t)ROWS * DMODEL;

    const int smem_gemm = 3 * 8192 * 4;                          // 98304
    const int smem_k3   = (2 * 64 * 68 + 2 * 64 * 68 + 64) * 4;  // 69888
    cudaFuncSetAttribute(gemm_tf32<0>, cudaFuncAttributeMaxDynamicSharedMemorySize, smem_gemm);
    cudaFuncSetAttribute(gemm_tf32<1>, cudaFuncAttributeMaxDynamicSharedMemorySize, smem_gemm);
    cudaFuncSetAttribute(ctx_norm_kernel, cudaFuncAttributeMaxDynamicSharedMemorySize, smem_k3);
    // Request the full shared-memory carveout so 3 CTAs (3x69888B) can be
    // resident per SM; without this the default carveout caps us at 2.
    cudaFuncSetAttribute(ctx_norm_kernel, cudaFuncAttributePreferredSharedMemoryCarveout, 100);

    round_prep<<<dim3(ROWS * DMODEL / 4 / 256, 5), 256>>>(x, Wq, Wk, Wv, Wo);
    gemm_tf32<0><<<dim3(DMODEL / 128, ROWS / 128, 3), 256, smem_gemm>>>(bq, bk, bv, nullptr);
    logits_exp_kernel<<<dim3(SEQ / 128, BH), 256>>>(attn);
    ctx_norm_kernel<<<dim3(SEQ / 64, BH), 256, smem_k3>>>(attn);
    gemm_tf32<1><<<dim3(DMODEL / 128, ROWS / 128, 1), 256, smem_gemm>>>(bo, nullptr, nullptr, out);
}